// round 2
// baseline (speedup 1.0000x reference)
#include <cuda_runtime.h>
#include <math.h>

// ---------------- problem constants ----------------
#define Bz   64
#define Dz   512
#define Hz   8
#define DHz  64
#define NL   6
#define Cz   1024
#define LKV  1025
#define FFz  2048
#define Tz   16
#define SAz  1088
#define NCH  16
#define EPSRN 1e-4f
#define ATT_SCALE 0.125f

// ---------------- scratch (__device__ globals: allocation-free) ----------------
__device__ float g_rel[LKV * Dz];                 // 2.1 MB  sin/cos rel-pos table (flipped)
__device__ float g_x[Bz * Dz];                    // current token x
__device__ float g_qkw[Bz * Hz * Dz];             // (Q+u)@wk_h  * n1w
__device__ float g_rv [Bz * Hz * Dz];             // (Q+v)@wr_h
__device__ float g_pm[Bz * NCH * Hz];             // partial softmax max
__device__ float g_ps[Bz * NCH * Hz];             // partial softmax sum
__device__ float g_pctx[Bz * NCH * Hz * Dz];      // 16 MB partial ctx
__device__ float g_h[Bz * Dz];                    // residual h
__device__ float g_y[Bz * Dz];                    // rmsnorm(h)*n2w
__device__ float g_ff[Bz * FFz];                  // FF hidden

// ---------------- helpers ----------------
__device__ __forceinline__ unsigned long long pk2(float2 v) {
    unsigned long long r;
    asm("mov.b64 %0, {%1,%2};" : "=l"(r) : "f"(v.x), "f"(v.y));
    return r;
}
__device__ __forceinline__ float2 up2(unsigned long long r) {
    float2 v;
    asm("mov.b64 {%0,%1}, %2;" : "=f"(v.x), "=f"(v.y) : "l"(r));
    return v;
}
// packed f32x2 FMA: c += a*b (2 FMAs / instr — doubles fp32 throughput on B300)
__device__ __forceinline__ void fma2(float2& c, float2 a, float2 b) {
    unsigned long long uc = pk2(c), ua = pk2(a), ub = pk2(b);
    asm("fma.rn.f32x2 %0, %1, %2, %0;" : "+l"(uc) : "l"(ua), "l"(ub));
    c = up2(uc);
}
__device__ __forceinline__ float wred(float v) {
#pragma unroll
    for (int o = 16; o; o >>= 1) v += __shfl_xor_sync(0xffffffffu, v, o);
    return v;
}

// ---------------- rel-pos table: rel[k] = emb[1024-k], emb = [sin | cos] ----------------
__global__ void k_rel() {
    int k = blockIdx.x, j = threadIdx.x;
    float p = (float)(1024 - k);
    int jj = (j < 256) ? j : j - 256;
    float invf = expf(-(float)jj * (9.210340371976184f / 256.0f)); // ln(10000)/256
    float a = p * invf;
    g_rel[k * Dz + j] = (j < 256) ? sinf(a) : cosf(a);
}

// ---------------- input projection: tok = cat(stoch, action_n)@in_w^T + b; x = silu(rmsnorm(tok)) ----------------
__global__ __launch_bounds__(256) void k_init(const float* __restrict__ stoch,
                                              const float* __restrict__ action,
                                              const float* __restrict__ in_w,
                                              const float* __restrict__ in_b,
                                              const float* __restrict__ in_norm_w) {
    __shared__ float cat[SAz];
    __shared__ float tok[Dz];
    __shared__ float red[9];
    int b = blockIdx.x, tid = threadIdx.x, w = tid >> 5, lane = tid & 31;
    for (int i = tid; i < 1024; i += 256) cat[i] = stoch[b * 1024 + i];
    if (tid < 64) {
        float a = action[b * 64 + tid];
        cat[1024 + tid] = a / fmaxf(fabsf(a), 1.0f);
    }
    __syncthreads();
    for (int it = 0; it < 64; it++) {
        int j = it * 8 + w;
        const float* wr_ = in_w + j * SAz;
        float acc = 0.f;
#pragma unroll 2
        for (int i = 0; i < 34; i++) { int idx = lane + 32 * i; acc = fmaf(cat[idx], wr_[idx], acc); }
        acc = wred(acc);
        if (lane == 0) tok[j] = acc + in_b[j];
    }
    __syncthreads();
    float ss = 0.f;
    for (int i = tid; i < Dz; i += 256) { float v = tok[i]; ss = fmaf(v, v, ss); }
    ss = wred(ss);
    if (lane == 0) red[w] = ss;
    __syncthreads();
    if (tid == 0) { float t = 0; for (int i = 0; i < 8; i++) t += red[i]; red[8] = rsqrtf(t / (float)Dz + EPSRN); }
    __syncthreads();
    float rstd = red[8];
    for (int i = tid; i < Dz; i += 256) {
        float yv = tok[i] * rstd * in_norm_w[i];
        g_x[b * Dz + i] = yv / (1.f + __expf(-yv)); // silu
    }
}

// ---------------- per-layer precompute: xn, Q, qkw=(Q+u)@wk_h*n1w, rv=(Q+v)@wr_h; write last cache row ----------------
__global__ __launch_bounds__(256) void k_q(int l,
                                           const float* __restrict__ n1w,
                                           const float* __restrict__ wq,
                                           const float* __restrict__ wk,
                                           const float* __restrict__ wr,
                                           const float* __restrict__ u,
                                           const float* __restrict__ v,
                                           float* __restrict__ ncache_l) {
    __shared__ float xs[Dz];
    __shared__ float xn[Dz];
    __shared__ float Qs[Dz];
    __shared__ float red[9];
    int b = blockIdx.x, tid = threadIdx.x, w = tid >> 5, lane = tid & 31;
    const float* n1 = n1w + l * Dz;
    float ss = 0.f;
    for (int i = tid; i < Dz; i += 256) { float vv = g_x[b * Dz + i]; xs[i] = vv; ss = fmaf(vv, vv, ss); }
    ss = wred(ss);
    if (lane == 0) red[w] = ss;
    __syncthreads();
    if (tid == 0) { float t = 0; for (int i = 0; i < 8; i++) t += red[i]; red[8] = rsqrtf(t / 512.f + EPSRN); }
    __syncthreads();
    float rstd = red[8];
    for (int i = tid; i < Dz; i += 256) xn[i] = xs[i] * rstd * n1[i];
    // new_cache[l][b][C-1] = raw x
    for (int i = tid; i < Dz; i += 256) ncache_l[((size_t)b * Cz + (Cz - 1)) * Dz + i] = xs[i];
    __syncthreads();
    // Q = xn @ wq^T
    const float* wql = wq + (size_t)l * Dz * Dz;
    for (int it = 0; it < 64; it++) {
        int j = it * 8 + w;
        const float2* wr2 = (const float2*)(wql + (size_t)j * Dz);
        const float2* x2 = (const float2*)xn;
        float2 acc = make_float2(0.f, 0.f);
#pragma unroll
        for (int i = 0; i < 8; i++) { int idx = lane + 32 * i; fma2(acc, x2[idx], wr2[idx]); }
        float a = wred(acc.x + acc.y);
        if (lane == 0) Qs[j] = a;
    }
    __syncthreads();
    // warp w == head w
    const float* wkl = wk + (size_t)l * Dz * Dz;
    const float* wrl = wr + (size_t)l * Dz * Dz;
    const float* ul = u + (size_t)l * Hz * DHz + w * DHz;
    const float* vl = v + (size_t)l * Hz * DHz + w * DHz;
    float2 ak[8], ar[8];
#pragma unroll
    for (int i = 0; i < 8; i++) { ak[i] = make_float2(0.f, 0.f); ar[i] = make_float2(0.f, 0.f); }
    for (int d = 0; d < 64; d++) {
        float qd = Qs[w * 64 + d];
        float2 ck2 = make_float2(qd + ul[d], qd + ul[d]);
        float2 cr2 = make_float2(qd + vl[d], qd + vl[d]);
        const float2* rk = (const float2*)(wkl + (size_t)(w * 64 + d) * Dz);
        const float2* rr = (const float2*)(wrl + (size_t)(w * 64 + d) * Dz);
#pragma unroll
        for (int i = 0; i < 8; i++) {
            int idx = lane + 32 * i;
            fma2(ak[i], ck2, rk[idx]);
            fma2(ar[i], cr2, rr[idx]);
        }
    }
    float2* qo = (float2*)(g_qkw + (size_t)(b * Hz + w) * Dz);
    float2* ro = (float2*)(g_rv + (size_t)(b * Hz + w) * Dz);
    const float2* n12 = (const float2*)n1;
#pragma unroll
    for (int i = 0; i < 8; i++) {
        int idx = lane + 32 * i;
        float2 nv = n12[idx];
        float2 t = ak[i];
        t.x *= nv.x; t.y *= nv.y;
        qo[idx] = t;
        ro[idx] = ar[i];
    }
}

// ---------------- THE streaming kernel: fused cache-shift + rmsnorm + scores + online softmax ctx ----------------
__global__ __launch_bounds__(256) void k_att(int l,
                                             const float* __restrict__ cache,
                                             float* __restrict__ ncache_l) {
    int c = blockIdx.x, b = blockIdx.y;
    int tid = threadIdx.x, w = tid >> 5, lane = tid & 31;
    __shared__ float2 rowb[2][256];
    __shared__ float2 relb[2][256];
    const float* cache_l = cache + (size_t)l * Bz * Cz * Dz;
    int start = c * 64;
    int cnt = (c == NCH - 1) ? 65 : 64;

    const float2* qp = (const float2*)(g_qkw + (size_t)(b * Hz + w) * Dz);
    const float2* rp = (const float2*)(g_rv + (size_t)(b * Hz + w) * Dz);
    float2 q2[8], r2[8];
#pragma unroll
    for (int i = 0; i < 8; i++) { q2[i] = qp[lane + 32 * i]; r2[i] = rp[lane + 32 * i]; }
    float m = -1e30f, s = 0.f;
    float2 ctx[8];
#pragma unroll
    for (int i = 0; i < 8; i++) ctx[i] = make_float2(0.f, 0.f);

    auto loadrow = [&](int slot, int k) {
        if (tid < 128) {
            const float4* src = (k < Cz) ? (const float4*)(cache_l + ((size_t)b * Cz + k) * Dz)
                                         : (const float4*)(g_x + b * Dz);
            float4 vv = src[tid];
            ((float4*)rowb[slot])[tid] = vv;
            if (k >= 1 && k < Cz)
                ((float4*)(ncache_l + ((size_t)b * Cz + (k - 1)) * Dz))[tid] = vv;
        } else {
            int t = tid - 128;
            ((float4*)relb[slot])[t] = ((const float4*)(g_rel + (size_t)k * Dz))[t];
        }
    };

    loadrow(0, start);
    for (int r = 0; r < cnt; r++) {
        __syncthreads();
        if (r + 1 < cnt) loadrow((r + 1) & 1, start + r + 1);
        int slot = r & 1;
        float2 kv2 = make_float2(0.f, 0.f), ss2 = make_float2(0.f, 0.f), rd2 = make_float2(0.f, 0.f);
        float2 rr[8];
#pragma unroll
        for (int i = 0; i < 8; i++) {
            int idx = lane + 32 * i;
            float2 rvv = rowb[slot][idx];
            rr[i] = rvv;
            fma2(kv2, q2[i], rvv);
            fma2(ss2, rvv, rvv);
            fma2(rd2, r2[i], relb[slot][idx]);
        }
        float kv = kv2.x + kv2.y, ssv = ss2.x + ss2.y, rd = rd2.x + rd2.y;
#pragma unroll
        for (int o = 16; o; o >>= 1) {
            kv += __shfl_xor_sync(0xffffffffu, kv, o);
            ssv += __shfl_xor_sync(0xffffffffu, ssv, o);
            rd += __shfl_xor_sync(0xffffffffu, rd, o);
        }
        float rstd = rsqrtf(ssv * (1.f / 512.f) + EPSRN);
        float score = ATT_SCALE * fmaf(rstd, kv, rd);
        float mn = fmaxf(m, score);
        float p = __expf(score - mn);
        if (mn > m && m > -1e29f) {
            float al = __expf(m - mn);
            s *= al;
#pragma unroll
            for (int i = 0; i < 8; i++) { ctx[i].x *= al; ctx[i].y *= al; }
        }
        m = mn;
        s += p;
        float pw = p * rstd; // weight on RAW row (n1w applied at merge)
        float2 pw2 = make_float2(pw, pw);
#pragma unroll
        for (int i = 0; i < 8; i++) fma2(ctx[i], pw2, rr[i]);
    }
    int pi = (b * NCH + c) * Hz + w;
    if (lane == 0) { g_pm[pi] = m; g_ps[pi] = s; }
    float2* po = (float2*)(g_pctx + (size_t)pi * Dz);
#pragma unroll
    for (int i = 0; i < 8; i++) po[lane + 32 * i] = ctx[i];
}

// ---------------- merge partials + attnV(wv) + wo + residual + rmsnorm(n2w) ----------------
__global__ __launch_bounds__(256) void k_out(int l,
                                             const float* __restrict__ n1w,
                                             const float* __restrict__ wv,
                                             const float* __restrict__ wo,
                                             const float* __restrict__ n2w) {
    __shared__ float ctxs[Hz * Dz]; // 16KB
    __shared__ float av[Dz];
    __shared__ float hb[Dz];
    __shared__ float red[9];
    int b = blockIdx.x, tid = threadIdx.x, w = tid >> 5, lane = tid & 31;
    // merge for head w
    float wm[NCH];
    float M = -1e30f;
#pragma unroll
    for (int ch = 0; ch < NCH; ch++) { wm[ch] = g_pm[(b * NCH + ch) * Hz + w]; M = fmaxf(M, wm[ch]); }
    float S = 0.f;
#pragma unroll
    for (int ch = 0; ch < NCH; ch++) { wm[ch] = __expf(wm[ch] - M); S += g_ps[(b * NCH + ch) * Hz + w] * wm[ch]; }
    float inv = 1.f / S;
    const float2* n12 = (const float2*)(n1w + l * Dz);
    float2* cs2 = (float2*)(ctxs + w * Dz);
#pragma unroll
    for (int i = 0; i < 8; i++) {
        int idx = lane + 32 * i;
        float2 acc = make_float2(0.f, 0.f);
#pragma unroll
        for (int ch = 0; ch < NCH; ch++) {
            float2 pv = ((const float2*)(g_pctx + (size_t)((b * NCH + ch) * Hz + w) * Dz))[idx];
            float2 w2 = make_float2(wm[ch], wm[ch]);
            fma2(acc, w2, pv);
        }
        float2 nv = n12[idx];
        acc.x *= inv * nv.x;
        acc.y *= inv * nv.y;
        cs2[idx] = acc;
    }
    __syncthreads();
    // attnV[i] = ctx[head(i)] . wv[i,:]   (head(i) == w for i in warp's range)
    const float* wvl = wv + (size_t)l * Dz * Dz;
    for (int it = 0; it < 64; it++) {
        int i = w * 64 + it;
        const float2* wr2 = (const float2*)(wvl + (size_t)i * Dz);
        const float2* c2 = (const float2*)(ctxs + w * Dz);
        float2 acc = make_float2(0.f, 0.f);
#pragma unroll
        for (int k = 0; k < 8; k++) { int idx = lane + 32 * k; fma2(acc, c2[idx], wr2[idx]); }
        float a = wred(acc.x + acc.y);
        if (lane == 0) av[i] = a;
    }
    __syncthreads();
    const float* wol = wo + (size_t)l * Dz * Dz;
    for (int it = 0; it < 64; it++) {
        int j = w * 64 + it;
        const float2* wr2 = (const float2*)(wol + (size_t)j * Dz);
        const float2* a2 = (const float2*)av;
        float2 acc = make_float2(0.f, 0.f);
#pragma unroll
        for (int k = 0; k < 8; k++) { int idx = lane + 32 * k; fma2(acc, a2[idx], wr2[idx]); }
        float a = wred(acc.x + acc.y);
        if (lane == 0) hb[j] = g_x[b * Dz + j] + a;
    }
    __syncthreads();
    float ss = 0.f;
    for (int i = tid; i < Dz; i += 256) { float vv = hb[i]; ss = fmaf(vv, vv, ss); }
    ss = wred(ss);
    if (lane == 0) red[w] = ss;
    __syncthreads();
    if (tid == 0) { float t = 0; for (int i = 0; i < 8; i++) t += red[i]; red[8] = rsqrtf(t / 512.f + EPSRN); }
    __syncthreads();
    float rstd = red[8];
    const float* n2 = n2w + l * Dz;
    for (int i = tid; i < Dz; i += 256) {
        g_h[b * Dz + i] = hb[i];
        g_y[b * Dz + i] = hb[i] * rstd * n2[i];
    }
}

// ---------------- FF1: gelu(y @ w1^T + b1) ----------------
__global__ __launch_bounds__(256) void k_ff1(int l, const float* __restrict__ w1, const float* __restrict__ b1) {
    __shared__ float ys[Dz];
    int b = blockIdx.y, tid = threadIdx.x, w = tid >> 5, lane = tid & 31;
    for (int i = tid; i < Dz; i += 256) ys[i] = g_y[b * Dz + i];
    __syncthreads();
    int f0 = blockIdx.x * 64;
    const float* w1l = w1 + (size_t)l * FFz * Dz;
    for (int it = 0; it < 8; it++) {
        int f = f0 + w * 8 + it;
        const float2* wr2 = (const float2*)(w1l + (size_t)f * Dz);
        const float2* y2 = (const float2*)ys;
        float2 acc = make_float2(0.f, 0.f);
#pragma unroll
        for (int k = 0; k < 8; k++) { int idx = lane + 32 * k; fma2(acc, y2[idx], wr2[idx]); }
        float a = wred(acc.x + acc.y);
        if (lane == 0) {
            a += b1[l * FFz + f];
            g_ff[b * FFz + f] = 0.5f * a * (1.f + erff(a * 0.70710678118654752f)); // exact gelu
        }
    }
}

// ---------------- FF2 + residual -> new x ----------------
__global__ __launch_bounds__(256) void k_ff2(int l, const float* __restrict__ w2, const float* __restrict__ b2) {
    __shared__ float zs[FFz];
    int b = blockIdx.y, tid = threadIdx.x, w = tid >> 5, lane = tid & 31;
    for (int i = tid; i < FFz; i += 256) zs[i] = g_ff[b * FFz + i];
    __syncthreads();
    int j0 = blockIdx.x * 64;
    const float* w2l = w2 + (size_t)l * Dz * FFz;
    for (int it = 0; it < 8; it++) {
        int j = j0 + w * 8 + it;
        const float2* wr2 = (const float2*)(w2l + (size_t)j * FFz);
        const float2* z2 = (const float2*)zs;
        float2 acc = make_float2(0.f, 0.f);
#pragma unroll
        for (int k = 0; k < 32; k++) { int idx = lane + 32 * k; fma2(acc, z2[idx], wr2[idx]); }
        float a = wred(acc.x + acc.y);
        if (lane == 0) g_x[b * Dz + j] = g_h[b * Dz + j] + a + b2[l * Dz + j];
    }
}

// ---------------- final: new_summary + new_deter ----------------
__global__ __launch_bounds__(256) void k_final(const float* __restrict__ summary,
                                               const float* __restrict__ onw,
                                               float* __restrict__ out_deter,
                                               float* __restrict__ out_summ) {
    int t = blockIdx.x, b = blockIdx.y, tid = threadIdx.x, w = tid >> 5, lane = tid & 31;
    __shared__ float row[Dz];
    __shared__ float red[9];
    const float* src = (t < Tz - 1) ? (summary + ((size_t)b * Tz + t + 1) * Dz) : (g_x + b * Dz);
    float ss = 0.f;
    for (int i = tid; i < Dz; i += 256) { float vv = src[i]; row[i] = vv; ss = fmaf(vv, vv, ss); }
    ss = wred(ss);
    if (lane == 0) red[w] = ss;
    __syncthreads();
    if (tid == 0) { float tt = 0; for (int i = 0; i < 8; i++) tt += red[i]; red[8] = rsqrtf(tt / 512.f + EPSRN); }
    __syncthreads();
    float rstd = red[8];
    for (int i = tid; i < Dz; i += 256) {
        out_summ[((size_t)b * Tz + t) * Dz + i] = row[i];
        out_deter[(size_t)b * (Tz * Dz) + t * Dz + i] = row[i] * rstd * onw[i];
    }
}

// ---------------- launch ----------------
extern "C" void kernel_launch(void* const* d_in, const int* in_sizes, int n_in,
                              void* d_out, int out_size) {
    (void)in_sizes; (void)n_in; (void)out_size;
    const float* stoch      = (const float*)d_in[0];
    const float* action     = (const float*)d_in[1];
    const float* cache      = (const float*)d_in[2];
    const float* summary    = (const float*)d_in[3];
    const float* in_w       = (const float*)d_in[4];
    const float* in_b       = (const float*)d_in[5];
    const float* in_norm_w  = (const float*)d_in[6];
    const float* n1w        = (const float*)d_in[7];
    const float* wq         = (const float*)d_in[8];
    const float* wk         = (const float*)d_in[9];
    const float* wv         = (const float*)d_in[10];
    const float* wr         = (const float*)d_in[11];
    const float* wo         = (const float*)d_in[12];
    const float* u          = (const float*)d_in[13];
    const float* v          = (const float*)d_in[14];
    const float* n2w        = (const float*)d_in[15];
    const float* ff_w1      = (const float*)d_in[16];
    const float* ff_b1      = (const float*)d_in[17];
    const float* ff_w2      = (const float*)d_in[18];
    const float* ff_b2      = (const float*)d_in[19];
    const float* out_norm_w = (const float*)d_in[20];

    float* out = (float*)d_out;
    float* out_deter = out;                                    // (B, T*D)
    float* out_cache = out + (size_t)Bz * Tz * Dz;             // (L,B,C,D)
    float* out_summ  = out_cache + (size_t)NL * Bz * Cz * Dz;  // (B,T,D)

    k_rel<<<LKV, 512>>>();
    k_init<<<Bz, 256>>>(stoch, action, in_w, in_b, in_norm_w);
    for (int l = 0; l < NL; l++) {
        float* nc_l = out_cache + (size_t)l * Bz * Cz * Dz;
        k_q<<<Bz, 256>>>(l, n1w, wq, wk, wr, u, v, nc_l);
        k_att<<<dim3(NCH, Bz), 256>>>(l, cache, nc_l);
        k_out<<<Bz, 256>>>(l, n1w, wv, wo, n2w);
        k_ff1<<<dim3(32, Bz), 256>>>(l, ff_w1, ff_b1);
        k_ff2<<<dim3(8, Bz), 256>>>(l, ff_w2, ff_b2);
    }
    k_final<<<dim3(Tz, Bz), 256>>>(summary, out_norm_w, out_deter, out_summ);
}

// round 4
// speedup vs baseline: 1.0294x; 1.0294x over previous
#include <cuda_runtime.h>
#include <math.h>

// ---------------- problem constants ----------------
#define Bz   64
#define Dz   512
#define Hz   8
#define DHz  64
#define NL   6
#define Cz   1024
#define LKV  1025
#define FFz  2048
#define Tz   16
#define SAz  1088
#define NCH  32
#define DEPTH 8
#define BDS  1032
#define EPSRN 1e-4f
#define ATT_SCALE 0.125f

// ---------------- scratch (__device__ globals: allocation-free) ----------------
__device__ float g_rel[LKV * Dz];                 // 2.1 MB  sin/cos rel-pos table (flipped)
__device__ float g_x[Bz * Dz];                    // current token x
__device__ float g_qkw[Bz * Hz * Dz];             // (Q+u)@wk_h  * n1w
__device__ float g_rv [Bz * Hz * Dz];             // (Q+v)@wr_h
__device__ float g_bd [Bz * Hz * BDS];            // precomputed BD scores (unscaled)
__device__ float g_pm[Bz * NCH * Hz];             // partial softmax max
__device__ float g_ps[Bz * NCH * Hz];             // partial softmax sum
__device__ float g_pctx[(size_t)Bz * NCH * Hz * Dz]; // 33 MB partial ctx
__device__ float g_ctxm[Bz * Hz * Dz];            // merged ctx (n1w applied)
__device__ float g_h[Bz * Dz];                    // residual h
__device__ float g_y[Bz * Dz];                    // rmsnorm(h)*n2w
__device__ float g_ff[Bz * FFz];                  // FF hidden

// ---------------- helpers ----------------
__device__ __forceinline__ unsigned long long pk2(float2 v) {
    unsigned long long r;
    asm("mov.b64 %0, {%1,%2};" : "=l"(r) : "f"(v.x), "f"(v.y));
    return r;
}
__device__ __forceinline__ float2 up2(unsigned long long r) {
    float2 v;
    asm("mov.b64 {%0,%1}, %2;" : "=f"(v.x), "=f"(v.y) : "l"(r));
    return v;
}
// packed f32x2 FMA: c += a*b
__device__ __forceinline__ void fma2(float2& c, float2 a, float2 b) {
    unsigned long long uc = pk2(c), ua = pk2(a), ub = pk2(b);
    asm("fma.rn.f32x2 %0, %1, %2, %0;" : "+l"(uc) : "l"(ua), "l"(ub));
    c = up2(uc);
}
__device__ __forceinline__ float wred(float v) {
#pragma unroll
    for (int o = 16; o; o >>= 1) v += __shfl_xor_sync(0xffffffffu, v, o);
    return v;
}
__device__ __forceinline__ void cpasync16(void* smem, const void* gmem) {
    unsigned sm = (unsigned)__cvta_generic_to_shared(smem);
    asm volatile("cp.async.cg.shared.global [%0], [%1], 16;" :: "r"(sm), "l"(gmem));
}
#define CP_COMMIT() asm volatile("cp.async.commit_group;")

// ---------------- rel-pos table: rel[k] = emb[1024-k], emb = [sin | cos] ----------------
__global__ void k_rel() {
    int k = blockIdx.x, j = threadIdx.x;
    float p = (float)(1024 - k);
    int jj = (j < 256) ? j : j - 256;
    float invf = expf(-(float)jj * (9.210340371976184f / 256.0f)); // ln(10000)/256
    float a = p * invf;
    g_rel[k * Dz + j] = (j < 256) ? sinf(a) : cosf(a);
}

// ---------------- input projection ----------------
__global__ __launch_bounds__(256) void k_init(const float* __restrict__ stoch,
                                              const float* __restrict__ action,
                                              const float* __restrict__ in_w,
                                              const float* __restrict__ in_b,
                                              const float* __restrict__ in_norm_w) {
    __shared__ float cat[SAz];
    __shared__ float tok[Dz];
    __shared__ float red[9];
    int b = blockIdx.x, tid = threadIdx.x, w = tid >> 5, lane = tid & 31;
    for (int i = tid; i < 1024; i += 256) cat[i] = stoch[b * 1024 + i];
    if (tid < 64) {
        float a = action[b * 64 + tid];
        cat[1024 + tid] = a / fmaxf(fabsf(a), 1.0f);
    }
    __syncthreads();
    for (int it = 0; it < 64; it++) {
        int j = it * 8 + w;
        const float* wr_ = in_w + j * SAz;
        float acc = 0.f;
#pragma unroll 2
        for (int i = 0; i < 34; i++) { int idx = lane + 32 * i; acc = fmaf(cat[idx], wr_[idx], acc); }
        acc = wred(acc);
        if (lane == 0) tok[j] = acc + in_b[j];
    }
    __syncthreads();
    float ss = 0.f;
    for (int i = tid; i < Dz; i += 256) { float v = tok[i]; ss = fmaf(v, v, ss); }
    ss = wred(ss);
    if (lane == 0) red[w] = ss;
    __syncthreads();
    if (tid == 0) { float t = 0; for (int i = 0; i < 8; i++) t += red[i]; red[8] = rsqrtf(t / (float)Dz + EPSRN); }
    __syncthreads();
    float rstd = red[8];
    for (int i = tid; i < Dz; i += 256) {
        float yv = tok[i] * rstd * in_norm_w[i];
        g_x[b * Dz + i] = yv / (1.f + __expf(-yv)); // silu
    }
}

// ---------------- per-layer precompute: xn, Q, qkw, rv; write last cache row ----------------
__global__ __launch_bounds__(256) void k_q(int l,
                                           const float* __restrict__ n1w,
                                           const float* __restrict__ wq,
                                           const float* __restrict__ wk,
                                           const float* __restrict__ wr,
                                           const float* __restrict__ u,
                                           const float* __restrict__ v,
                                           float* __restrict__ ncache_l) {
    __shared__ float xs[Dz];
    __shared__ float xn[Dz];
    __shared__ float Qs[Dz];
    __shared__ float red[9];
    int b = blockIdx.x, tid = threadIdx.x, w = tid >> 5, lane = tid & 31;
    const float* n1 = n1w + l * Dz;
    float ss = 0.f;
    for (int i = tid; i < Dz; i += 256) { float vv = g_x[b * Dz + i]; xs[i] = vv; ss = fmaf(vv, vv, ss); }
    ss = wred(ss);
    if (lane == 0) red[w] = ss;
    __syncthreads();
    if (tid == 0) { float t = 0; for (int i = 0; i < 8; i++) t += red[i]; red[8] = rsqrtf(t / 512.f + EPSRN); }
    __syncthreads();
    float rstd = red[8];
    for (int i = tid; i < Dz; i += 256) xn[i] = xs[i] * rstd * n1[i];
    for (int i = tid; i < Dz; i += 256) ncache_l[((size_t)b * Cz + (Cz - 1)) * Dz + i] = xs[i];
    __syncthreads();
    // Q = xn @ wq^T
    const float* wql = wq + (size_t)l * Dz * Dz;
    for (int it = 0; it < 64; it++) {
        int j = it * 8 + w;
        const float2* wr2 = (const float2*)(wql + (size_t)j * Dz);
        const float2* x2 = (const float2*)xn;
        float2 acc = make_float2(0.f, 0.f);
#pragma unroll
        for (int i = 0; i < 8; i++) { int idx = lane + 32 * i; fma2(acc, x2[idx], wr2[idx]); }
        float a = wred(acc.x + acc.y);
        if (lane == 0) Qs[j] = a;
    }
    __syncthreads();
    // warp w == head w
    const float* wkl = wk + (size_t)l * Dz * Dz;
    const float* wrl = wr + (size_t)l * Dz * Dz;
    const float* ul = u + (size_t)l * Hz * DHz + w * DHz;
    const float* vl = v + (size_t)l * Hz * DHz + w * DHz;
    float2 ak[8], ar[8];
#pragma unroll
    for (int i = 0; i < 8; i++) { ak[i] = make_float2(0.f, 0.f); ar[i] = make_float2(0.f, 0.f); }
    for (int d = 0; d < 64; d++) {
        float qd = Qs[w * 64 + d];
        float2 ck2 = make_float2(qd + ul[d], qd + ul[d]);
        float2 cr2 = make_float2(qd + vl[d], qd + vl[d]);
        const float2* rk = (const float2*)(wkl + (size_t)(w * 64 + d) * Dz);
        const float2* rr = (const float2*)(wrl + (size_t)(w * 64 + d) * Dz);
#pragma unroll
        for (int i = 0; i < 8; i++) {
            int idx = lane + 32 * i;
            fma2(ak[i], ck2, rk[idx]);
            fma2(ar[i], cr2, rr[idx]);
        }
    }
    float2* qo = (float2*)(g_qkw + (size_t)(b * Hz + w) * Dz);
    float2* ro = (float2*)(g_rv + (size_t)(b * Hz + w) * Dz);
    const float2* n12 = (const float2*)n1;
#pragma unroll
    for (int i = 0; i < 8; i++) {
        int idx = lane + 32 * i;
        float2 nv = n12[idx];
        float2 t = ak[i];
        t.x *= nv.x; t.y *= nv.y;
        qo[idx] = t;
        ro[idx] = ar[i];
    }
}

// ---------------- BD precompute: bd[b,h,k] = rv[b,h] . rel[k]  (unscaled) ----------------
__global__ __launch_bounds__(256) void k_bd() {
    int kc = blockIdx.x, b = blockIdx.y;
    int tid = threadIdx.x, w = tid >> 5, lane = tid & 31;
    __shared__ __align__(16) float relb[4][Dz]; // 8KB, depth-4 ring
    int start = kc * 128;
    int cnt = (kc == 7) ? 129 : 128;
    const float2* rp = (const float2*)(g_rv + (size_t)(b * Hz + w) * Dz);
    float2 r2[8];
#pragma unroll
    for (int i = 0; i < 8; i++) r2[i] = rp[lane + 32 * i];
    float* bdo = g_bd + (size_t)(b * Hz + w) * BDS;
    // prologue
#pragma unroll
    for (int d = 0; d < 4; d++) {
        if (tid < 128 && d < cnt)
            cpasync16(&relb[d][tid * 4], g_rel + (size_t)(start + d) * Dz + tid * 4);
        CP_COMMIT();
    }
    for (int r = 0; r < cnt; r++) {
        asm volatile("cp.async.wait_group 3;");
        __syncthreads();
        int slot = r & 3;
        float2 rd2 = make_float2(0.f, 0.f);
        const float2* rel2 = (const float2*)relb[slot];
#pragma unroll
        for (int i = 0; i < 8; i++) fma2(rd2, r2[i], rel2[lane + 32 * i]);
        float rd = wred(rd2.x + rd2.y);
        if (lane == 0) bdo[start + r] = rd;
        __syncthreads();
        int kn = start + r + 4;
        if (tid < 128 && r + 4 < cnt)
            cpasync16(&relb[slot][tid * 4], g_rel + (size_t)kn * Dz + tid * 4);
        CP_COMMIT();
    }
}

// ---------------- streaming attention: cache shift + rmsnorm + score + online softmax ctx ----------------
__global__ __launch_bounds__(256) void k_att(int l,
                                             const float* __restrict__ cache,
                                             float* __restrict__ ncache_l) {
    int c = blockIdx.x, b = blockIdx.y;
    int tid = threadIdx.x, w = tid >> 5, lane = tid & 31;
    __shared__ __align__(16) float rowb[DEPTH][Dz]; // 16KB ring
    const float* cache_l = cache + (size_t)l * Bz * Cz * Dz;
    int start = c * 32;
    int cnt = (c == NCH - 1) ? 33 : 32;

    const float2* qp = (const float2*)(g_qkw + (size_t)(b * Hz + w) * Dz);
    float2 q2[8];
#pragma unroll
    for (int i = 0; i < 8; i++) q2[i] = qp[lane + 32 * i];
    const float* bdp = g_bd + (size_t)(b * Hz + w) * BDS;
    float m = -1e30f, s = 0.f;
    float2 ctx[8];
#pragma unroll
    for (int i = 0; i < 8; i++) ctx[i] = make_float2(0.f, 0.f);

    // prologue: DEPTH rows in flight
#pragma unroll
    for (int d = 0; d < DEPTH; d++) {
        int k = start + d;
        if (tid < 128 && d < cnt) {
            const float* src = (k < Cz) ? cache_l + ((size_t)b * Cz + k) * Dz + tid * 4
                                        : g_x + b * Dz + tid * 4;
            cpasync16(&rowb[d][tid * 4], src);
        }
        CP_COMMIT();
    }

    for (int r = 0; r < cnt; r++) {
        asm volatile("cp.async.wait_group 7;");
        __syncthreads();
        int slot = r & (DEPTH - 1);
        int k = start + r;
        float2 kv2 = make_float2(0.f, 0.f), ss2 = make_float2(0.f, 0.f);
        float2 rr[8];
        const float2* row2 = (const float2*)rowb[slot];
#pragma unroll
        for (int i = 0; i < 8; i++) {
            float2 rvv = row2[lane + 32 * i];
            rr[i] = rvv;
            fma2(kv2, q2[i], rvv);
            fma2(ss2, rvv, rvv);
        }
        float kv = kv2.x + kv2.y, ssv = ss2.x + ss2.y;
#pragma unroll
        for (int o = 16; o; o >>= 1) {
            kv += __shfl_xor_sync(0xffffffffu, kv, o);
            ssv += __shfl_xor_sync(0xffffffffu, ssv, o);
        }
        float rstd = rsqrtf(ssv * (1.f / 512.f) + EPSRN);
        float score = ATT_SCALE * fmaf(rstd, kv, bdp[k]);
        float mn = fmaxf(m, score);
        float p = __expf(score - mn);
        if (mn > m && m > -1e29f) {
            float al = __expf(m - mn);
            s *= al;
#pragma unroll
            for (int i = 0; i < 8; i++) { ctx[i].x *= al; ctx[i].y *= al; }
        }
        m = mn;
        s += p;
        float pw = p * rstd; // weight on RAW row (n1w applied at merge)
        float2 pw2 = make_float2(pw, pw);
#pragma unroll
        for (int i = 0; i < 8; i++) fma2(ctx[i], pw2, rr[i]);
        // fused cache shift: write row k to new_cache[k-1]
        if (k >= 1 && k < Cz)
            ((float2*)(ncache_l + ((size_t)b * Cz + (k - 1)) * Dz))[tid] = row2[tid];
        __syncthreads();
        // issue next row into freed slot
        int kn = start + r + DEPTH;
        if (tid < 128 && r + DEPTH < cnt) {
            const float* src = (kn < Cz) ? cache_l + ((size_t)b * Cz + kn) * Dz + tid * 4
                                         : g_x + b * Dz + tid * 4;
            cpasync16(&rowb[slot][tid * 4], src);
        }
        CP_COMMIT();
    }
    int pi = (b * NCH + c) * Hz + w;
    if (lane == 0) { g_pm[pi] = m; g_ps[pi] = s; }
    float2* po = (float2*)(g_pctx + (size_t)pi * Dz);
#pragma unroll
    for (int i = 0; i < 8; i++) po[lane + 32 * i] = ctx[i];
}

// ---------------- merge softmax partials -> g_ctxm (n1w & 1/S applied) ----------------
__global__ __launch_bounds__(256) void k_merge(int l, const float* __restrict__ n1w) {
    int b = blockIdx.x, h = blockIdx.y;
    int tid = threadIdx.x;
    __shared__ float wch[NCH];
    __shared__ float sinv;
    if (tid < 32) {
        float mv = g_pm[(b * NCH + tid) * Hz + h];
        float M = mv;
#pragma unroll
        for (int o = 16; o; o >>= 1) M = fmaxf(M, __shfl_xor_sync(0xffffffffu, M, o));
        float e = __expf(mv - M);
        float sv = g_ps[(b * NCH + tid) * Hz + h] * e;
#pragma unroll
        for (int o = 16; o; o >>= 1) sv += __shfl_xor_sync(0xffffffffu, sv, o);
        wch[tid] = e;
        if (tid == 0) sinv = 1.f / sv;
    }
    __syncthreads();
    float2 acc = make_float2(0.f, 0.f);
#pragma unroll
    for (int ch = 0; ch < NCH; ch++) {
        float2 pv = ((const float2*)(g_pctx + (size_t)((b * NCH + ch) * Hz + h) * Dz))[tid];
        float2 w2 = make_float2(wch[ch], wch[ch]);
        fma2(acc, w2, pv);
    }
    float inv = sinv;
    float2 nv = ((const float2*)(n1w + l * Dz))[tid];
    acc.x *= inv * nv.x;
    acc.y *= inv * nv.y;
    ((float2*)(g_ctxm + (size_t)(b * Hz + h) * Dz))[tid] = acc;
}

// ---------------- attnV(wv) + wo + residual + rmsnorm(n2w) ----------------
__global__ __launch_bounds__(256) void k_out(int l,
                                             const float* __restrict__ wv,
                                             const float* __restrict__ wo,
                                             const float* __restrict__ n2w) {
    __shared__ float ctxs[Hz * Dz]; // 16KB
    __shared__ float av[Dz];
    __shared__ float hb[Dz];
    __shared__ float red[9];
    int b = blockIdx.x, tid = threadIdx.x, w = tid >> 5, lane = tid & 31;
    for (int i = tid; i < Hz * Dz; i += 256) ctxs[i] = g_ctxm[(size_t)b * Hz * Dz + i];
    __syncthreads();
    const float* wvl = wv + (size_t)l * Dz * Dz;
    for (int it = 0; it < 64; it++) {
        int i = w * 64 + it;
        const float2* wr2 = (const float2*)(wvl + (size_t)i * Dz);
        const float2* c2 = (const float2*)(ctxs + w * Dz);
        float2 acc = make_float2(0.f, 0.f);
#pragma unroll
        for (int k = 0; k < 8; k++) { int idx = lane + 32 * k; fma2(acc, c2[idx], wr2[idx]); }
        float a = wred(acc.x + acc.y);
        if (lane == 0) av[i] = a;
    }
    __syncthreads();
    const float* wol = wo + (size_t)l * Dz * Dz;
    for (int it = 0; it < 64; it++) {
        int j = w * 64 + it;
        const float2* wr2 = (const float2*)(wol + (size_t)j * Dz);
        const float2* a2 = (const float2*)av;
        float2 acc = make_float2(0.f, 0.f);
#pragma unroll
        for (int k = 0; k < 8; k++) { int idx = lane + 32 * k; fma2(acc, a2[idx], wr2[idx]); }
        float a = wred(acc.x + acc.y);
        if (lane == 0) hb[j] = g_x[b * Dz + j] + a;
    }
    __syncthreads();
    float ss = 0.f;
    for (int i = tid; i < Dz; i += 256) { float vv = hb[i]; ss = fmaf(vv, vv, ss); }
    ss = wred(ss);
    if (lane == 0) red[w] = ss;
    __syncthreads();
    if (tid == 0) { float t = 0; for (int i = 0; i < 8; i++) t += red[i]; red[8] = rsqrtf(t / 512.f + EPSRN); }
    __syncthreads();
    float rstd = red[8];
    const float* n2 = n2w + l * Dz;
    for (int i = tid; i < Dz; i += 256) {
        g_h[b * Dz + i] = hb[i];
        g_y[b * Dz + i] = hb[i] * rstd * n2[i];
    }
}

// ---------------- FF1: gelu(y @ w1^T + b1), 8 batches per block ----------------
__global__ __launch_bounds__(256) void k_ff1(int l, const float* __restrict__ w1, const float* __restrict__ b1) {
    __shared__ __align__(16) float ys[8][Dz]; // 16KB
    int b0 = blockIdx.y * 8, tid = threadIdx.x, w = tid >> 5, lane = tid & 31;
#pragma unroll
    for (int i = 0; i < 4; i++)
        ((float4*)ys)[tid + 256 * i] = ((const float4*)(g_y + (size_t)b0 * Dz))[tid + 256 * i];
    __syncthreads();
    int f0 = blockIdx.x * 64;
    const float* w1l = w1 + (size_t)l * FFz * Dz;
    for (int it = 0; it < 8; it++) {
        int f = f0 + w * 8 + it;
        const float2* wr2 = (const float2*)(w1l + (size_t)f * Dz);
        float2 wv_[8];
#pragma unroll
        for (int i = 0; i < 8; i++) wv_[i] = wr2[lane + 32 * i];
        float2 acc[8];
#pragma unroll
        for (int bb = 0; bb < 8; bb++) acc[bb] = make_float2(0.f, 0.f);
#pragma unroll
        for (int i = 0; i < 8; i++) {
            int idx = lane + 32 * i;
#pragma unroll
            for (int bb = 0; bb < 8; bb++) fma2(acc[bb], wv_[i], ((const float2*)ys[bb])[idx]);
        }
#pragma unroll
        for (int bb = 0; bb < 8; bb++) {
            float a = wred(acc[bb].x + acc[bb].y);
            if (lane == 0) {
                a += b1[l * FFz + f];
                g_ff[(size_t)(b0 + bb) * FFz + f] = 0.5f * a * (1.f + erff(a * 0.70710678118654752f));
            }
        }
    }
}

// ---------------- FF2 + residual -> new x, 4 batches per block ----------------
__global__ __launch_bounds__(256) void k_ff2(int l, const float* __restrict__ w2, const float* __restrict__ b2) {
    __shared__ __align__(16) float zs[4][FFz]; // 32KB
    int b0 = blockIdx.y * 4, tid = threadIdx.x, w = tid >> 5, lane = tid & 31;
#pragma unroll
    for (int i = 0; i < 8; i++)
        ((float4*)zs)[tid + 256 * i] = ((const float4*)(g_ff + (size_t)b0 * FFz))[tid + 256 * i];
    __syncthreads();
    int j0 = blockIdx.x * 64;
    const float* w2l = w2 + (size_t)l * Dz * FFz;
    for (int it = 0; it < 8; it++) {
        int j = j0 + w * 8 + it;
        const float2* wr2 = (const float2*)(w2l + (size_t)j * FFz);
#pragma unroll
        for (int bb = 0; bb < 4; bb++) {
            const float2* z2 = (const float2*)zs[bb];
            float2 acc = make_float2(0.f, 0.f);
#pragma unroll
            for (int k = 0; k < 32; k++) { int idx = lane + 32 * k; fma2(acc, z2[idx], wr2[idx]); }
            float a = wred(acc.x + acc.y);
            if (lane == 0) g_x[(size_t)(b0 + bb) * Dz + j] = g_h[(size_t)(b0 + bb) * Dz + j] + a + b2[l * Dz + j];
        }
    }
}

// ---------------- final: new_summary + new_deter ----------------
__global__ __launch_bounds__(256) void k_final(const float* __restrict__ summary,
                                               const float* __restrict__ onw,
                                               float* __restrict__ out_deter,
                                               float* __restrict__ out_summ) {
    int t = blockIdx.x, b = blockIdx.y, tid = threadIdx.x, w = tid >> 5, lane = tid & 31;
    __shared__ float row[Dz];
    __shared__ float red[9];
    const float* src = (t < Tz - 1) ? (summary + ((size_t)b * Tz + t + 1) * Dz) : (g_x + b * Dz);
    float ss = 0.f;
    for (int i = tid; i < Dz; i += 256) { float vv = src[i]; row[i] = vv; ss = fmaf(vv, vv, ss); }
    ss = wred(ss);
    if (lane == 0) red[w] = ss;
    __syncthreads();
    if (tid == 0) { float tt = 0; for (int i = 0; i < 8; i++) tt += red[i]; red[8] = rsqrtf(tt / 512.f + EPSRN); }
    __syncthreads();
    float rstd = red[8];
    for (int i = tid; i < Dz; i += 256) {
        out_summ[((size_t)b * Tz + t) * Dz + i] = row[i];
        out_deter[(size_t)b * (Tz * Dz) + t * Dz + i] = row[i] * rstd * onw[i];
    }
}

// ---------------- launch ----------------
extern "C" void kernel_launch(void* const* d_in, const int* in_sizes, int n_in,
                              void* d_out, int out_size) {
    (void)in_sizes; (void)n_in; (void)out_size;
    const float* stoch      = (const float*)d_in[0];
    const float* action     = (const float*)d_in[1];
    const float* cache      = (const float*)d_in[2];
    const float* summary    = (const float*)d_in[3];
    const float* in_w       = (const float*)d_in[4];
    const float* in_b       = (const float*)d_in[5];
    const float* in_norm_w  = (const float*)d_in[6];
    const float* n1w        = (const float*)d_in[7];
    const float* wq         = (const float*)d_in[8];
    const float* wk         = (const float*)d_in[9];
    const float* wv         = (const float*)d_in[10];
    const float* wr         = (const float*)d_in[11];
    const float* wo         = (const float*)d_in[12];
    const float* u          = (const float*)d_in[13];
    const float* v          = (const float*)d_in[14];
    const float* n2w        = (const float*)d_in[15];
    const float* ff_w1      = (const float*)d_in[16];
    const float* ff_b1      = (const float*)d_in[17];
    const float* ff_w2      = (const float*)d_in[18];
    const float* ff_b2      = (const float*)d_in[19];
    const float* out_norm_w = (const float*)d_in[20];

    float* out = (float*)d_out;
    float* out_deter = out;                                    // (B, T*D)
    float* out_cache = out + (size_t)Bz * Tz * Dz;             // (L,B,C,D)
    float* out_summ  = out_cache + (size_t)NL * Bz * Cz * Dz;  // (B,T,D)

    k_rel<<<LKV, 512>>>();
    k_init<<<Bz, 256>>>(stoch, action, in_w, in_b, in_norm_w);
    for (int l = 0; l < NL; l++) {
        float* nc_l = out_cache + (size_t)l * Bz * Cz * Dz;
        k_q<<<Bz, 256>>>(l, n1w, wq, wk, wr, u, v, nc_l);
        k_bd<<<dim3(8, Bz), 256>>>();
        k_att<<<dim3(NCH, Bz), 256>>>(l, cache, nc_l);
        k_merge<<<dim3(Bz, Hz), 256>>>(l, n1w);
        k_out<<<Bz, 256>>>(l, wv, wo, n2w);
        k_ff1<<<dim3(32, 8), 256>>>(l, ff_w1, ff_b1);
        k_ff2<<<dim3(8, 16), 256>>>(l, ff_w2, ff_b2);
    }
    k_final<<<dim3(Tz, Bz), 256>>>(summary, out_norm_w, out_deter, out_summ);
}

// round 5
// speedup vs baseline: 1.8759x; 1.8223x over previous
#include <cuda_runtime.h>
#include <math.h>

// ---------------- problem constants ----------------
#define Bz   64
#define Dz   512
#define Hz   8
#define DHz  64
#define NL   6
#define Cz   1024
#define LKV  1025
#define FFz  2048
#define Tz   16
#define SAz  1088
#define NCH  32
#define DEPTH 8
#define BDS  1032
#define EPSRN 1e-4f
#define ATT_SCALE 0.125f

// ---------------- scratch (__device__ globals) ----------------
__device__ float g_rel[LKV * Dz];
__device__ float g_cat[Bz * SAz];
__device__ float g_tok[Bz * Dz];
__device__ float g_x[Bz * Dz];
__device__ float g_xn[Bz * Dz];
__device__ float g_quk[Bz * Dz];
__device__ float g_qur[Bz * Dz];
__device__ float g_qkw[Bz * Hz * Dz];
__device__ float g_rv [Bz * Hz * Dz];
__device__ float g_bd [Bz * Hz * BDS];
__device__ float g_pm[Bz * NCH * Hz];
__device__ float g_ps[Bz * NCH * Hz];
__device__ float g_pctx[(size_t)Bz * NCH * Hz * Dz];
__device__ float g_ctxm[Bz * Hz * Dz];
__device__ float g_av[Bz * Dz];
__device__ float g_h[Bz * Dz];
__device__ float g_y[Bz * Dz];
__device__ float g_ff[Bz * FFz];
__device__ float g_part[4 * Bz * Dz];

// ---------------- helpers ----------------
__device__ __forceinline__ unsigned long long pk2(float2 v) {
    unsigned long long r;
    asm("mov.b64 %0, {%1,%2};" : "=l"(r) : "f"(v.x), "f"(v.y));
    return r;
}
__device__ __forceinline__ float2 up2(unsigned long long r) {
    float2 v;
    asm("mov.b64 {%0,%1}, %2;" : "=f"(v.x), "=f"(v.y) : "l"(r));
    return v;
}
__device__ __forceinline__ void fma2(float2& c, float2 a, float2 b) {
    unsigned long long uc = pk2(c), ua = pk2(a), ub = pk2(b);
    asm("fma.rn.f32x2 %0, %1, %2, %0;" : "+l"(uc) : "l"(ua), "l"(ub));
    c = up2(uc);
}
__device__ __forceinline__ float wred(float v) {
#pragma unroll
    for (int o = 16; o; o >>= 1) v += __shfl_xor_sync(0xffffffffu, v, o);
    return v;
}
__device__ __forceinline__ void cpasync16(void* smem, const void* gmem) {
    unsigned sm = (unsigned)__cvta_generic_to_shared(smem);
    asm volatile("cp.async.cg.shared.global [%0], [%1], 16;" :: "r"(sm), "l"(gmem));
}
#define CP_COMMIT() asm volatile("cp.async.commit_group;")

// =====================================================================
// Generic 64-row tiled GEMM:  C[b, j] = sum_k A[b,k] * W(j,k)
//   A: 64 rows x Ktot cols (lda), block A base = A + jt*aXs + by*aYs
//   W layout0: W[j][k] row-major (ldw = K stride); row index jt*64+r
//   W layout1: W[k][j] (ldw = N stride), base += by*wYs
//   modes: 0 store, 1 bias+gelu, 3 dual C=v+e1[jg],C2=v+e2[jg],
//          4 scale C=v*e1[jg], 5 bias C=v+e1[jg], 6 residual C=v+e2[ci]
// =====================================================================
__global__ __launch_bounds__(256) void k_mm(
    const float* __restrict__ A, int lda, int aXs, int aYs,
    const float* __restrict__ W, int ldw, int wYs, int wLayout,
    float* __restrict__ C, int ldc, int cYs,
    int Ktot, int Nmax, int mode,
    const float* __restrict__ e1, const float* __restrict__ e2,
    float* __restrict__ C2)
{
    __shared__ __align__(16) float As[64][68];
    __shared__ __align__(16) float Ws[64][68];
    int jt = blockIdx.x, by = blockIdx.y;
    const float* Ab = A + (size_t)jt * aXs + (size_t)by * aYs;
    const float* Wb = W + (size_t)by * wYs;
    float* Cb = C + (size_t)by * cYs;
    int tid = threadIdx.x;
    int tx = tid & 15, ty = tid >> 4;
    float2 acc[4][2];
#pragma unroll
    for (int i = 0; i < 4; i++) { acc[i][0] = make_float2(0.f, 0.f); acc[i][1] = make_float2(0.f, 0.f); }
    int lr = tid >> 2;            // 0..63
    int lc = (tid & 3) * 16;      // 0,16,32,48

    for (int kc = 0; kc < Ktot; kc += 64) {
        { // A tile transpose: As[k][b]
            const float4* src = (const float4*)(Ab + (size_t)lr * lda + kc + lc);
#pragma unroll
            for (int q = 0; q < 4; q++) {
                float4 vv = src[q];
                As[lc + q * 4 + 0][lr] = vv.x; As[lc + q * 4 + 1][lr] = vv.y;
                As[lc + q * 4 + 2][lr] = vv.z; As[lc + q * 4 + 3][lr] = vv.w;
            }
        }
        if (wLayout == 0) { // W[j][k] -> transpose into Ws[k][j]
            int jr = jt * 64 + lr; if (jr >= Nmax) jr = Nmax - 1;
            const float4* src = (const float4*)(Wb + (size_t)jr * ldw + kc + lc);
#pragma unroll
            for (int q = 0; q < 4; q++) {
                float4 vv = src[q];
                Ws[lc + q * 4 + 0][lr] = vv.x; Ws[lc + q * 4 + 1][lr] = vv.y;
                Ws[lc + q * 4 + 2][lr] = vv.z; Ws[lc + q * 4 + 3][lr] = vv.w;
            }
        } else {            // W[k][j] -> direct copy Ws[k][j]
            const float4* src = (const float4*)(Wb + (size_t)(kc + lr) * ldw + jt * 64 + lc);
            float4* dst = (float4*)&Ws[lr][lc];
#pragma unroll
            for (int q = 0; q < 4; q++) dst[q] = src[q];
        }
        __syncthreads();
#pragma unroll 16
        for (int kk = 0; kk < 64; kk++) {
            float4 a4 = *(const float4*)&As[kk][ty * 4];
            float4 w4 = *(const float4*)&Ws[kk][tx * 4];
            float2 w01 = make_float2(w4.x, w4.y), w23 = make_float2(w4.z, w4.w);
            fma2(acc[0][0], make_float2(a4.x, a4.x), w01);
            fma2(acc[0][1], make_float2(a4.x, a4.x), w23);
            fma2(acc[1][0], make_float2(a4.y, a4.y), w01);
            fma2(acc[1][1], make_float2(a4.y, a4.y), w23);
            fma2(acc[2][0], make_float2(a4.z, a4.z), w01);
            fma2(acc[2][1], make_float2(a4.z, a4.z), w23);
            fma2(acc[3][0], make_float2(a4.w, a4.w), w01);
            fma2(acc[3][1], make_float2(a4.w, a4.w), w23);
        }
        __syncthreads();
    }
    int b0 = ty * 4, j0 = tx * 4;
#pragma unroll
    for (int i = 0; i < 4; i++) {
        float vals[4] = {acc[i][0].x, acc[i][0].y, acc[i][1].x, acc[i][1].y};
#pragma unroll
        for (int u = 0; u < 4; u++) {
            int jg = jt * 64 + j0 + u;
            if (jg >= Nmax) continue;
            size_t ci = (size_t)(b0 + i) * ldc + jg;
            float vv = vals[u];
            if (mode == 0)      Cb[ci] = vv;
            else if (mode == 1) { vv += e1[jg]; Cb[ci] = 0.5f * vv * (1.f + erff(vv * 0.70710678118654752f)); }
            else if (mode == 3) { Cb[ci] = vv + e1[jg]; C2[ci] = vv + e2[jg]; }
            else if (mode == 4) Cb[ci] = vv * e1[jg];
            else if (mode == 5) Cb[ci] = vv + e1[jg];
            else if (mode == 6) Cb[ci] = vv + e2[ci];
        }
    }
}

// ---------------- rel-pos table ----------------
__global__ void k_rel() {
    int k = blockIdx.x, j = threadIdx.x;
    float p = (float)(1024 - k);
    int jj = (j < 256) ? j : j - 256;
    float invf = expf(-(float)jj * (9.210340371976184f / 256.0f));
    float a = p * invf;
    g_rel[k * Dz + j] = (j < 256) ? sinf(a) : cosf(a);
}

// ---------------- cat(stoch, action_norm) ----------------
__global__ __launch_bounds__(256) void k_prep(const float* __restrict__ stoch,
                                              const float* __restrict__ action) {
    int b = blockIdx.x, tid = threadIdx.x;
    for (int i = tid; i < 1024; i += 256) g_cat[b * SAz + i] = stoch[b * 1024 + i];
    if (tid < 64) {
        float a = action[b * 64 + tid];
        g_cat[b * SAz + 1024 + tid] = a / fmaxf(fabsf(a), 1.0f);
    }
}

// ---------------- silu(rmsnorm(tok)) -> g_x ----------------
__global__ __launch_bounds__(256) void k_silu(const float* __restrict__ inw) {
    int b = blockIdx.x, tid = threadIdx.x, w = tid >> 5, lane = tid & 31;
    __shared__ float red[9];
    float2 xv = ((const float2*)(g_tok + b * Dz))[tid];
    float ss = fmaf(xv.x, xv.x, xv.y * xv.y);
    ss = wred(ss);
    if (lane == 0) red[w] = ss;
    __syncthreads();
    if (tid == 0) { float t = 0; for (int i = 0; i < 8; i++) t += red[i]; red[8] = rsqrtf(t / 512.f + EPSRN); }
    __syncthreads();
    float rstd = red[8];
    float2 nv = ((const float2*)inw)[tid];
    float yx = xv.x * rstd * nv.x, yy = xv.y * rstd * nv.y;
    float2 o = make_float2(yx / (1.f + __expf(-yx)), yy / (1.f + __expf(-yy)));
    ((float2*)(g_x + b * Dz))[tid] = o;
}

// ---------------- xn = rmsnorm(x)*n1, write last cache row ----------------
__global__ __launch_bounds__(256) void k_xn(int l, const float* __restrict__ n1w,
                                            float* __restrict__ ncache_l) {
    int b = blockIdx.x, tid = threadIdx.x, w = tid >> 5, lane = tid & 31;
    __shared__ float red[9];
    float2 xv = ((const float2*)(g_x + b * Dz))[tid];
    float ss = fmaf(xv.x, xv.x, xv.y * xv.y);
    ss = wred(ss);
    if (lane == 0) red[w] = ss;
    __syncthreads();
    if (tid == 0) { float t = 0; for (int i = 0; i < 8; i++) t += red[i]; red[8] = rsqrtf(t / 512.f + EPSRN); }
    __syncthreads();
    float rstd = red[8];
    float2 nv = ((const float2*)(n1w + l * Dz))[tid];
    ((float2*)(g_xn + b * Dz))[tid] = make_float2(xv.x * rstd * nv.x, xv.y * rstd * nv.y);
    ((float2*)(ncache_l + ((size_t)b * Cz + (Cz - 1)) * Dz))[tid] = xv;
}

// ---------------- y = rmsnorm(h)*n2 ----------------
__global__ __launch_bounds__(256) void k_h(int l, const float* __restrict__ n2w) {
    int b = blockIdx.x, tid = threadIdx.x, w = tid >> 5, lane = tid & 31;
    __shared__ float red[9];
    float2 hv = ((const float2*)(g_h + b * Dz))[tid];
    float ss = fmaf(hv.x, hv.x, hv.y * hv.y);
    ss = wred(ss);
    if (lane == 0) red[w] = ss;
    __syncthreads();
    if (tid == 0) { float t = 0; for (int i = 0; i < 8; i++) t += red[i]; red[8] = rsqrtf(t / 512.f + EPSRN); }
    __syncthreads();
    float rstd = red[8];
    float2 nv = ((const float2*)(n2w + l * Dz))[tid];
    ((float2*)(g_y + b * Dz))[tid] = make_float2(hv.x * rstd * nv.x, hv.y * rstd * nv.y);
}

// ---------------- streaming attention (unchanged from R3) ----------------
__global__ __launch_bounds__(256) void k_att(int l,
                                             const float* __restrict__ cache,
                                             float* __restrict__ ncache_l) {
    int c = blockIdx.x, b = blockIdx.y;
    int tid = threadIdx.x, w = tid >> 5, lane = tid & 31;
    __shared__ __align__(16) float rowb[DEPTH][Dz];
    const float* cache_l = cache + (size_t)l * Bz * Cz * Dz;
    int start = c * 32;
    int cnt = (c == NCH - 1) ? 33 : 32;

    const float2* qp = (const float2*)(g_qkw + (size_t)(b * Hz + w) * Dz);
    float2 q2[8];
#pragma unroll
    for (int i = 0; i < 8; i++) q2[i] = qp[lane + 32 * i];
    const float* bdp = g_bd + (size_t)(b * Hz + w) * BDS;
    float m = -1e30f, s = 0.f;
    float2 ctx[8];
#pragma unroll
    for (int i = 0; i < 8; i++) ctx[i] = make_float2(0.f, 0.f);

#pragma unroll
    for (int d = 0; d < DEPTH; d++) {
        int k = start + d;
        if (tid < 128 && d < cnt) {
            const float* src = (k < Cz) ? cache_l + ((size_t)b * Cz + k) * Dz + tid * 4
                                        : g_x + b * Dz + tid * 4;
            cpasync16(&rowb[d][tid * 4], src);
        }
        CP_COMMIT();
    }

    for (int r = 0; r < cnt; r++) {
        asm volatile("cp.async.wait_group 7;");
        __syncthreads();
        int slot = r & (DEPTH - 1);
        int k = start + r;
        float2 kv2 = make_float2(0.f, 0.f), ss2 = make_float2(0.f, 0.f);
        float2 rr[8];
        const float2* row2 = (const float2*)rowb[slot];
#pragma unroll
        for (int i = 0; i < 8; i++) {
            float2 rvv = row2[lane + 32 * i];
            rr[i] = rvv;
            fma2(kv2, q2[i], rvv);
            fma2(ss2, rvv, rvv);
        }
        float kv = kv2.x + kv2.y, ssv = ss2.x + ss2.y;
#pragma unroll
        for (int o = 16; o; o >>= 1) {
            kv += __shfl_xor_sync(0xffffffffu, kv, o);
            ssv += __shfl_xor_sync(0xffffffffu, ssv, o);
        }
        float rstd = rsqrtf(ssv * (1.f / 512.f) + EPSRN);
        float score = ATT_SCALE * fmaf(rstd, kv, bdp[k]);
        float mn = fmaxf(m, score);
        float p = __expf(score - mn);
        if (mn > m && m > -1e29f) {
            float al = __expf(m - mn);
            s *= al;
#pragma unroll
            for (int i = 0; i < 8; i++) { ctx[i].x *= al; ctx[i].y *= al; }
        }
        m = mn;
        s += p;
        float pw = p * rstd;
        float2 pw2 = make_float2(pw, pw);
#pragma unroll
        for (int i = 0; i < 8; i++) fma2(ctx[i], pw2, rr[i]);
        if (k >= 1 && k < Cz)
            ((float2*)(ncache_l + ((size_t)b * Cz + (k - 1)) * Dz))[tid] = row2[tid];
        __syncthreads();
        int kn = start + r + DEPTH;
        if (tid < 128 && r + DEPTH < cnt) {
            const float* src = (kn < Cz) ? cache_l + ((size_t)b * Cz + kn) * Dz + tid * 4
                                         : g_x + b * Dz + tid * 4;
            cpasync16(&rowb[slot][tid * 4], src);
        }
        CP_COMMIT();
    }
    int pi = (b * NCH + c) * Hz + w;
    if (lane == 0) { g_pm[pi] = m; g_ps[pi] = s; }
    float2* po = (float2*)(g_pctx + (size_t)pi * Dz);
#pragma unroll
    for (int i = 0; i < 8; i++) po[lane + 32 * i] = ctx[i];
}

// ---------------- merge softmax partials -> g_ctxm (n1w & 1/S applied) ----------------
__global__ __launch_bounds__(256) void k_merge(int l, const float* __restrict__ n1w) {
    int b = blockIdx.x, h = blockIdx.y;
    int tid = threadIdx.x;
    __shared__ float wch[NCH];
    __shared__ float sinv;
    if (tid < 32) {
        float mv = g_pm[(b * NCH + tid) * Hz + h];
        float M = mv;
#pragma unroll
        for (int o = 16; o; o >>= 1) M = fmaxf(M, __shfl_xor_sync(0xffffffffu, M, o));
        float e = __expf(mv - M);
        float sv = g_ps[(b * NCH + tid) * Hz + h] * e;
#pragma unroll
        for (int o = 16; o; o >>= 1) sv += __shfl_xor_sync(0xffffffffu, sv, o);
        wch[tid] = e;
        if (tid == 0) sinv = 1.f / sv;
    }
    __syncthreads();
    float2 acc = make_float2(0.f, 0.f);
#pragma unroll
    for (int ch = 0; ch < NCH; ch++) {
        float2 pv = ((const float2*)(g_pctx + (size_t)((b * NCH + ch) * Hz + h) * Dz))[tid];
        float2 w2 = make_float2(wch[ch], wch[ch]);
        fma2(acc, w2, pv);
    }
    float inv = sinv;
    float2 nv = ((const float2*)(n1w + l * Dz))[tid];
    acc.x *= inv * nv.x;
    acc.y *= inv * nv.y;
    ((float2*)(g_ctxm + (size_t)(b * Hz + h) * Dz))[tid] = acc;
}

// ---------------- ff2 partial reduce + bias + residual -> new x ----------------
__global__ __launch_bounds__(256) void k_ff2red(const float* __restrict__ b2l) {
    int b = blockIdx.x, tid = threadIdx.x;
    float2 s = ((const float2*)(g_part + (size_t)b * Dz))[tid];
#pragma unroll
    for (int ks = 1; ks < 4; ks++) {
        float2 p = ((const float2*)(g_part + (size_t)ks * Bz * Dz + (size_t)b * Dz))[tid];
        s.x += p.x; s.y += p.y;
    }
    float2 bb = ((const float2*)b2l)[tid];
    float2 hh = ((const float2*)(g_h + (size_t)b * Dz))[tid];
    ((float2*)(g_x + (size_t)b * Dz))[tid] = make_float2(s.x + bb.x + hh.x, s.y + bb.y + hh.y);
}

// ---------------- final ----------------
__global__ __launch_bounds__(256) void k_final(const float* __restrict__ summary,
                                               const float* __restrict__ onw,
                                               float* __restrict__ out_deter,
                                               float* __restrict__ out_summ) {
    int t = blockIdx.x, b = blockIdx.y, tid = threadIdx.x, w = tid >> 5, lane = tid & 31;
    __shared__ float row[Dz];
    __shared__ float red[9];
    const float* src = (t < Tz - 1) ? (summary + ((size_t)b * Tz + t + 1) * Dz) : (g_x + b * Dz);
    float ss = 0.f;
    for (int i = tid; i < Dz; i += 256) { float vv = src[i]; row[i] = vv; ss = fmaf(vv, vv, ss); }
    ss = wred(ss);
    if (lane == 0) red[w] = ss;
    __syncthreads();
    if (tid == 0) { float tt = 0; for (int i = 0; i < 8; i++) tt += red[i]; red[8] = rsqrtf(tt / 512.f + EPSRN); }
    __syncthreads();
    float rstd = red[8];
    for (int i = tid; i < Dz; i += 256) {
        out_summ[((size_t)b * Tz + t) * Dz + i] = row[i];
        out_deter[(size_t)b * (Tz * Dz) + t * Dz + i] = row[i] * rstd * onw[i];
    }
}

// ---------------- launch ----------------
extern "C" void kernel_launch(void* const* d_in, const int* in_sizes, int n_in,
                              void* d_out, int out_size) {
    (void)in_sizes; (void)n_in; (void)out_size;
    const float* stoch      = (const float*)d_in[0];
    const float* action     = (const float*)d_in[1];
    const float* cache      = (const float*)d_in[2];
    const float* summary    = (const float*)d_in[3];
    const float* in_w       = (const float*)d_in[4];
    const float* in_b       = (const float*)d_in[5];
    const float* in_norm_w  = (const float*)d_in[6];
    const float* n1w        = (const float*)d_in[7];
    const float* wq         = (const float*)d_in[8];
    const float* wk         = (const float*)d_in[9];
    const float* wv         = (const float*)d_in[10];
    const float* wr         = (const float*)d_in[11];
    const float* wo         = (const float*)d_in[12];
    const float* u          = (const float*)d_in[13];
    const float* v          = (const float*)d_in[14];
    const float* n2w        = (const float*)d_in[15];
    const float* ff_w1      = (const float*)d_in[16];
    const float* ff_b1      = (const float*)d_in[17];
    const float* ff_w2      = (const float*)d_in[18];
    const float* ff_b2      = (const float*)d_in[19];
    const float* out_norm_w = (const float*)d_in[20];

    float* out = (float*)d_out;
    float* out_deter = out;
    float* out_cache = out + (size_t)Bz * Tz * Dz;
    float* out_summ  = out_cache + (size_t)NL * Bz * Cz * Dz;

    float *p_cat, *p_tok, *p_x, *p_xn, *p_quk, *p_qur, *p_qkw, *p_rv, *p_bd,
          *p_rel, *p_ctxm, *p_av, *p_h, *p_y, *p_ff, *p_part;
    cudaGetSymbolAddress((void**)&p_cat,  g_cat);
    cudaGetSymbolAddress((void**)&p_tok,  g_tok);
    cudaGetSymbolAddress((void**)&p_x,    g_x);
    cudaGetSymbolAddress((void**)&p_xn,   g_xn);
    cudaGetSymbolAddress((void**)&p_quk,  g_quk);
    cudaGetSymbolAddress((void**)&p_qur,  g_qur);
    cudaGetSymbolAddress((void**)&p_qkw,  g_qkw);
    cudaGetSymbolAddress((void**)&p_rv,   g_rv);
    cudaGetSymbolAddress((void**)&p_bd,   g_bd);
    cudaGetSymbolAddress((void**)&p_rel,  g_rel);
    cudaGetSymbolAddress((void**)&p_ctxm, g_ctxm);
    cudaGetSymbolAddress((void**)&p_av,   g_av);
    cudaGetSymbolAddress((void**)&p_h,    g_h);
    cudaGetSymbolAddress((void**)&p_y,    g_y);
    cudaGetSymbolAddress((void**)&p_ff,   g_ff);
    cudaGetSymbolAddress((void**)&p_part, g_part);

    k_rel<<<LKV, 512>>>();
    k_prep<<<Bz, 256>>>(stoch, action);
    // tok = cat @ in_w^T + in_b
    k_mm<<<8, 256>>>(p_cat, SAz, 0, 0, in_w, SAz, 0, 0, p_tok, Dz, 0,
                     SAz, Dz, 5, in_b, nullptr, nullptr);
    k_silu<<<Bz, 256>>>(in_norm_w);

    for (int l = 0; l < NL; l++) {
        float* nc_l = out_cache + (size_t)l * Bz * Cz * Dz;
        const float* wql = wq + (size_t)l * Dz * Dz;
        const float* wkl = wk + (size_t)l * Dz * Dz;
        const float* wvl = wv + (size_t)l * Dz * Dz;
        const float* wrl = wr + (size_t)l * Dz * Dz;
        const float* wol = wo + (size_t)l * Dz * Dz;

        k_xn<<<Bz, 256>>>(l, n1w, nc_l);
        // Q = xn@wq^T; Quk = Q+u, Qur = Q+v
        k_mm<<<8, 256>>>(p_xn, Dz, 0, 0, wql, Dz, 0, 0, p_quk, Dz, 0,
                         Dz, Dz, 3, u + l * Dz, v + l * Dz, p_qur);
        // qkw[b,h,:] = Quk[b, h-slice] @ wk[h-rows, :] * n1
        k_mm<<<dim3(8, 8), 256>>>(p_quk, Dz, 0, 64, wkl, Dz, 64 * Dz, 1,
                                  p_qkw, Hz * Dz, Dz, 64, Dz, 4,
                                  n1w + l * Dz, nullptr, nullptr);
        // rv[b,h,:] = Qur[b, h-slice] @ wr[h-rows, :]
        k_mm<<<dim3(8, 8), 256>>>(p_qur, Dz, 0, 64, wrl, Dz, 64 * Dz, 1,
                                  p_rv, Hz * Dz, Dz, 64, Dz, 0,
                                  nullptr, nullptr, nullptr);
        // bd(512x1025) = rv @ rel^T
        k_mm<<<dim3(17, 8), 256>>>(p_rv, Dz, 0, 64 * Dz, p_rel, Dz, 0, 0,
                                   p_bd, BDS, 64 * BDS, Dz, LKV, 0,
                                   nullptr, nullptr, nullptr);
        k_att<<<dim3(NCH, Bz), 256>>>(l, cache, nc_l);
        k_merge<<<dim3(Bz, Hz), 256>>>(l, n1w);
        // av[b,i] = ctx[b, h=i/64, :] . wv[i,:]
        k_mm<<<8, 256>>>(p_ctxm, Hz * Dz, Dz, 0, wvl, Dz, 0, 0, p_av, Dz, 0,
                         Dz, Dz, 0, nullptr, nullptr, nullptr);
        // h = x + av @ wo^T
        k_mm<<<8, 256>>>(p_av, Dz, 0, 0, wol, Dz, 0, 0, p_h, Dz, 0,
                         Dz, Dz, 6, nullptr, p_x, nullptr);
        k_h<<<Bz, 256>>>(l, n2w);
        // ff hidden = gelu(y @ w1^T + b1)
        k_mm<<<32, 256>>>(p_y, Dz, 0, 0, ff_w1 + (size_t)l * FFz * Dz, Dz, 0, 0,
                          p_ff, FFz, 0, Dz, FFz, 1,
                          ff_b1 + (size_t)l * FFz, nullptr, nullptr);
        // ff2 split-K partials
        k_mm<<<dim3(8, 4), 256>>>(p_ff, FFz, 0, 512, ff_w2 + (size_t)l * Dz * FFz, FFz, 512, 0,
                                  p_part, Dz, Bz * Dz, 512, Dz, 0,
                                  nullptr, nullptr, nullptr);
        k_ff2red<<<Bz, 256>>>(ff_b2 + (size_t)l * Dz);
    }
    k_final<<<dim3(Tz, Bz), 256>>>(summary, out_norm_w, out_deter, out_summ);
}

// round 6
// speedup vs baseline: 1.9277x; 1.0276x over previous
#include <cuda_runtime.h>
#include <math.h>

// ---------------- problem constants ----------------
#define Bz   64
#define Dz   512
#define Hz   8
#define DHz  64
#define NL   6
#define Cz   1024
#define LKV  1025
#define FFz  2048
#define Tz   16
#define SAz  1088
#define NCH  32
#define DEPTH 8
#define BDS  1032
#define EPSRN 1e-4f
#define ATT_SCALE 0.125f

// ---------------- scratch (__device__ globals) ----------------
__device__ float g_rel[LKV * Dz];
__device__ float g_cat[Bz * SAz];
__device__ float g_tok[Bz * Dz];
__device__ float g_x[Bz * Dz];
__device__ float g_quk[Bz * Dz];
__device__ float g_qur[Bz * Dz];
__device__ float g_qkw[Bz * Hz * Dz];
__device__ float g_rv [Bz * Hz * Dz];
__device__ float g_bd [Bz * Hz * BDS];
__device__ float g_pm[Bz * NCH * Hz];
__device__ float g_ps[Bz * NCH * Hz];
__device__ float g_pctx[(size_t)Bz * NCH * Hz * Dz];
__device__ float g_av[Bz * Dz];
__device__ float g_h[Bz * Dz];
__device__ float g_ff[Bz * FFz];
__device__ float g_part[4 * Bz * Dz];

// ---------------- helpers ----------------
__device__ __forceinline__ unsigned long long pk2(float2 v) {
    unsigned long long r;
    asm("mov.b64 %0, {%1,%2};" : "=l"(r) : "f"(v.x), "f"(v.y));
    return r;
}
__device__ __forceinline__ float2 up2(unsigned long long r) {
    float2 v;
    asm("mov.b64 {%0,%1}, %2;" : "=f"(v.x), "=f"(v.y) : "l"(r));
    return v;
}
__device__ __forceinline__ void fma2(float2& c, float2 a, float2 b) {
    unsigned long long uc = pk2(c), ua = pk2(a), ub = pk2(b);
    asm("fma.rn.f32x2 %0, %1, %2, %0;" : "+l"(uc) : "l"(ua), "l"(ub));
    c = up2(uc);
}
__device__ __forceinline__ float wred(float v) {
#pragma unroll
    for (int o = 16; o; o >>= 1) v += __shfl_xor_sync(0xffffffffu, v, o);
    return v;
}
__device__ __forceinline__ void cpasync16(void* smem, const void* gmem) {
    unsigned sm = (unsigned)__cvta_generic_to_shared(smem);
    asm volatile("cp.async.cg.shared.global [%0], [%1], 16;" :: "r"(sm), "l"(gmem));
}
#define CP_COMMIT() asm volatile("cp.async.commit_group;")

// =====================================================================
// Generic 64-row tiled GEMM:  C[b, j] = sum_k A[b,k] * W(j,k)
//   modes: 0 store, 1 bias+gelu, 3 dual C=v+e1[jg],C2=v+e2[jg],
//          4 scale C=v*e1[jg], 5 bias C=v+e1[jg], 6 residual C=v+e2[ci]
//   nw != null: A rows are rmsnorm'd on the fly: As = A[b][k]*rstd[b]*nw[k]
//               (requires Ktot==512 == full row, lda==512)
//   gridDim.z == 2 && blockIdx.z == 1: use Az2/Wz2/Cz2/modez2 (fused pair)
// =====================================================================
__global__ __launch_bounds__(256) void k_mm(
    const float* __restrict__ A, int lda, int aXs, int aYs,
    const float* __restrict__ W, int ldw, int wYs, int wLayout,
    float* __restrict__ C, int ldc, int cYs,
    int Ktot, int Nmax, int mode,
    const float* __restrict__ e1, const float* __restrict__ e2,
    float* __restrict__ C2, const float* __restrict__ nw,
    const float* __restrict__ Az2, const float* __restrict__ Wz2,
    float* __restrict__ Cz2, int modez2)
{
    __shared__ __align__(16) float As[64][68];
    __shared__ __align__(16) float Ws[64][68];
    __shared__ float rstd_s[64];
    if (blockIdx.z == 1) { A = Az2; W = Wz2; C = Cz2; mode = modez2; e1 = nullptr; }
    int jt = blockIdx.x, by = blockIdx.y;
    const float* Ab = A + (size_t)jt * aXs + (size_t)by * aYs;
    const float* Wb = W + (size_t)by * wYs;
    float* Cb = C + (size_t)by * cYs;
    int tid = threadIdx.x;
    int tx = tid & 15, ty = tid >> 4;
    float2 acc[4][2];
#pragma unroll
    for (int i = 0; i < 4; i++) { acc[i][0] = make_float2(0.f, 0.f); acc[i][1] = make_float2(0.f, 0.f); }
    int lr = tid >> 2;            // 0..63
    int lc = (tid & 3) * 16;      // 0,16,32,48

    if (nw) { // fused rmsnorm pre-pass over full 512-col rows
        int row = tid >> 2, seg = tid & 3;
        const float4* p = (const float4*)(Ab + (size_t)row * lda + seg * 128);
        float ssum = 0.f;
#pragma unroll
        for (int i = 0; i < 32; i++) {
            float4 vq = p[i];
            ssum += vq.x * vq.x + vq.y * vq.y + vq.z * vq.z + vq.w * vq.w;
        }
        ssum += __shfl_xor_sync(0xffffffffu, ssum, 1);
        ssum += __shfl_xor_sync(0xffffffffu, ssum, 2);
        if (seg == 0) rstd_s[row] = rsqrtf(ssum * (1.f / 512.f) + EPSRN);
        __syncthreads();
    }

    for (int kc = 0; kc < Ktot; kc += 64) {
        { // A tile transpose: As[k][b]
            const float4* src = (const float4*)(Ab + (size_t)lr * lda + kc + lc);
            float rsc = nw ? rstd_s[lr] : 1.f;
#pragma unroll
            for (int q = 0; q < 4; q++) {
                float4 vv = src[q];
                if (nw) {
                    float4 nv4 = *(const float4*)(nw + kc + lc + q * 4);
                    vv.x *= rsc * nv4.x; vv.y *= rsc * nv4.y;
                    vv.z *= rsc * nv4.z; vv.w *= rsc * nv4.w;
                }
                As[lc + q * 4 + 0][lr] = vv.x; As[lc + q * 4 + 1][lr] = vv.y;
                As[lc + q * 4 + 2][lr] = vv.z; As[lc + q * 4 + 3][lr] = vv.w;
            }
        }
        if (wLayout == 0) { // W[j][k] -> transpose into Ws[k][j]
            int jr = jt * 64 + lr; if (jr >= Nmax) jr = Nmax - 1;
            const float4* src = (const float4*)(Wb + (size_t)jr * ldw + kc + lc);
#pragma unroll
            for (int q = 0; q < 4; q++) {
                float4 vv = src[q];
                Ws[lc + q * 4 + 0][lr] = vv.x; Ws[lc + q * 4 + 1][lr] = vv.y;
                Ws[lc + q * 4 + 2][lr] = vv.z; Ws[lc + q * 4 + 3][lr] = vv.w;
            }
        } else {            // W[k][j] -> direct copy Ws[k][j]
            const float4* src = (const float4*)(Wb + (size_t)(kc + lr) * ldw + jt * 64 + lc);
            float4* dst = (float4*)&Ws[lr][lc];
#pragma unroll
            for (int q = 0; q < 4; q++) dst[q] = src[q];
        }
        __syncthreads();
#pragma unroll 16
        for (int kk = 0; kk < 64; kk++) {
            float4 a4 = *(const float4*)&As[kk][ty * 4];
            float4 w4 = *(const float4*)&Ws[kk][tx * 4];
            float2 w01 = make_float2(w4.x, w4.y), w23 = make_float2(w4.z, w4.w);
            fma2(acc[0][0], make_float2(a4.x, a4.x), w01);
            fma2(acc[0][1], make_float2(a4.x, a4.x), w23);
            fma2(acc[1][0], make_float2(a4.y, a4.y), w01);
            fma2(acc[1][1], make_float2(a4.y, a4.y), w23);
            fma2(acc[2][0], make_float2(a4.z, a4.z), w01);
            fma2(acc[2][1], make_float2(a4.z, a4.z), w23);
            fma2(acc[3][0], make_float2(a4.w, a4.w), w01);
            fma2(acc[3][1], make_float2(a4.w, a4.w), w23);
        }
        __syncthreads();
    }
    int b0 = ty * 4, j0 = tx * 4;
#pragma unroll
    for (int i = 0; i < 4; i++) {
        float vals[4] = {acc[i][0].x, acc[i][0].y, acc[i][1].x, acc[i][1].y};
#pragma unroll
        for (int u = 0; u < 4; u++) {
            int jg = jt * 64 + j0 + u;
            if (jg >= Nmax) continue;
            size_t ci = (size_t)(b0 + i) * ldc + jg;
            float vv = vals[u];
            if (mode == 0)      Cb[ci] = vv;
            else if (mode == 1) { vv += e1[jg]; Cb[ci] = 0.5f * vv * (1.f + erff(vv * 0.70710678118654752f)); }
            else if (mode == 3) { Cb[ci] = vv + e1[jg]; C2[ci] = vv + e2[jg]; }
            else if (mode == 4) Cb[ci] = vv * e1[jg];
            else if (mode == 5) Cb[ci] = vv + e1[jg];
            else if (mode == 6) Cb[ci] = vv + e2[ci];
        }
    }
}

// ---------------- rel-pos table ----------------
__global__ void k_rel() {
    int k = blockIdx.x, j = threadIdx.x;
    float p = (float)(1024 - k);
    int jj = (j < 256) ? j : j - 256;
    float invf = expf(-(float)jj * (9.210340371976184f / 256.0f));
    float a = p * invf;
    g_rel[k * Dz + j] = (j < 256) ? sinf(a) : cosf(a);
}

// ---------------- cat(stoch, action_norm) ----------------
__global__ __launch_bounds__(256) void k_prep(const float* __restrict__ stoch,
                                              const float* __restrict__ action) {
    int b = blockIdx.x, tid = threadIdx.x;
    for (int i = tid; i < 1024; i += 256) g_cat[b * SAz + i] = stoch[b * 1024 + i];
    if (tid < 64) {
        float a = action[b * 64 + tid];
        g_cat[b * SAz + 1024 + tid] = a / fmaxf(fabsf(a), 1.0f);
    }
}

// ---------------- silu(rmsnorm(tok)) -> g_x ----------------
__global__ __launch_bounds__(256) void k_silu(const float* __restrict__ inw) {
    int b = blockIdx.x, tid = threadIdx.x, w = tid >> 5, lane = tid & 31;
    __shared__ float red[9];
    float2 xv = ((const float2*)(g_tok + b * Dz))[tid];
    float ss = fmaf(xv.x, xv.x, xv.y * xv.y);
    ss = wred(ss);
    if (lane == 0) red[w] = ss;
    __syncthreads();
    if (tid == 0) { float t = 0; for (int i = 0; i < 8; i++) t += red[i]; red[8] = rsqrtf(t / 512.f + EPSRN); }
    __syncthreads();
    float rstd = red[8];
    float2 nv = ((const float2*)inw)[tid];
    float yx = xv.x * rstd * nv.x, yy = xv.y * rstd * nv.y;
    float2 o = make_float2(yx / (1.f + __expf(-yx)), yy / (1.f + __expf(-yy)));
    ((float2*)(g_x + b * Dz))[tid] = o;
}

// ---------------- streaming attention: 1 sync/row, 7 rows in flight ----------------
__global__ __launch_bounds__(256) void k_att(int l,
                                             const float* __restrict__ cache,
                                             float* __restrict__ ncache_l) {
    int c = blockIdx.x, b = blockIdx.y;
    int tid = threadIdx.x, w = tid >> 5, lane = tid & 31;
    __shared__ __align__(16) float rowb[DEPTH][Dz];
    const float* cache_l = cache + (size_t)l * Bz * Cz * Dz;
    int start = c * 32;
    int cnt = (c == NCH - 1) ? 33 : 32;

    const float2* qp = (const float2*)(g_qkw + (size_t)(b * Hz + w) * Dz);
    float2 q2[8];
#pragma unroll
    for (int i = 0; i < 8; i++) q2[i] = qp[lane + 32 * i];
    const float* bdp = g_bd + (size_t)(b * Hz + w) * BDS;
    float m = -1e30f, s = 0.f;
    float2 ctx[8];
#pragma unroll
    for (int i = 0; i < 8; i++) ctx[i] = make_float2(0.f, 0.f);

    // prologue: 7 rows in flight
#pragma unroll
    for (int d = 0; d < 7; d++) {
        int k = start + d;
        if (tid < 128 && d < cnt) {
            const float* src = (k < Cz) ? cache_l + ((size_t)b * Cz + k) * Dz + tid * 4
                                        : g_x + b * Dz + tid * 4;
            cpasync16(&rowb[d][tid * 4], src);
        }
        CP_COMMIT();
    }

    for (int r = 0; r < cnt; r++) {
        asm volatile("cp.async.wait_group 6;");
        __syncthreads();
        // issue next row into slot (r+7)&7 == (r-1)&7 (safe: all threads past compute r-1)
        int kn = start + r + 7;
        if (tid < 128 && r + 7 < cnt) {
            const float* src = (kn < Cz) ? cache_l + ((size_t)b * Cz + kn) * Dz + tid * 4
                                         : g_x + b * Dz + tid * 4;
            cpasync16(&rowb[(r + 7) & (DEPTH - 1)][tid * 4], src);
        }
        CP_COMMIT();
        int slot = r & (DEPTH - 1);
        int k = start + r;
        float2 kv2 = make_float2(0.f, 0.f), ss2 = make_float2(0.f, 0.f);
        float2 rr[8];
        const float2* row2 = (const float2*)rowb[slot];
#pragma unroll
        for (int i = 0; i < 8; i++) {
            float2 rvv = row2[lane + 32 * i];
            rr[i] = rvv;
            fma2(kv2, q2[i], rvv);
            fma2(ss2, rvv, rvv);
        }
        float kv = kv2.x + kv2.y, ssv = ss2.x + ss2.y;
#pragma unroll
        for (int o = 16; o; o >>= 1) {
            kv += __shfl_xor_sync(0xffffffffu, kv, o);
            ssv += __shfl_xor_sync(0xffffffffu, ssv, o);
        }
        float rstd = rsqrtf(ssv * (1.f / 512.f) + EPSRN);
        float score = ATT_SCALE * fmaf(rstd, kv, bdp[k]);
        float mn = fmaxf(m, score);
        float p = __expf(score - mn);
        if (mn > m && m > -1e29f) {
            float al = __expf(m - mn);
            s *= al;
#pragma unroll
            for (int i = 0; i < 8; i++) { ctx[i].x *= al; ctx[i].y *= al; }
        }
        m = mn;
        s += p;
        float pw = p * rstd;
        float2 pw2 = make_float2(pw, pw);
#pragma unroll
        for (int i = 0; i < 8; i++) fma2(ctx[i], pw2, rr[i]);
        // fused cache shift (k in [1,Cz] -> new_cache row k-1); k==Cz writes x
        if (k >= 1)
            __stcs(((float2*)(ncache_l + ((size_t)b * Cz + (k - 1)) * Dz)) + tid, row2[tid]);
    }
    int pi = (b * NCH + c) * Hz + w;
    if (lane == 0) { g_pm[pi] = m; g_ps[pi] = s; }
    float2* po = (float2*)(g_pctx + (size_t)pi * Dz);
#pragma unroll
    for (int i = 0; i < 8; i++) po[lane + 32 * i] = ctx[i];
}

// ---------------- merge softmax partials + av GEMV (fused) ----------------
__global__ __launch_bounds__(256) void k_mav(int l, const float* __restrict__ n1w,
                                             const float* __restrict__ wv) {
    int b = blockIdx.x, h = blockIdx.y;
    int tid = threadIdx.x, w = tid >> 5, lane = tid & 31;
    __shared__ float wch[NCH];
    __shared__ float sinv;
    __shared__ __align__(16) float ctxs[Dz];
    if (tid < 32) {
        float mv = g_pm[(b * NCH + tid) * Hz + h];
        float M = mv;
#pragma unroll
        for (int o = 16; o; o >>= 1) M = fmaxf(M, __shfl_xor_sync(0xffffffffu, M, o));
        float e = __expf(mv - M);
        float sv = g_ps[(b * NCH + tid) * Hz + h] * e;
#pragma unroll
        for (int o = 16; o; o >>= 1) sv += __shfl_xor_sync(0xffffffffu, sv, o);
        wch[tid] = e;
        if (tid == 0) sinv = 1.f / sv;
    }
    __syncthreads();
    float2 acc = make_float2(0.f, 0.f);
#pragma unroll
    for (int ch = 0; ch < NCH; ch++) {
        float2 pv = ((const float2*)(g_pctx + (size_t)((b * NCH + ch) * Hz + h) * Dz))[tid];
        float2 w2 = make_float2(wch[ch], wch[ch]);
        fma2(acc, w2, pv);
    }
    float inv = sinv;
    float2 nv = ((const float2*)(n1w + l * Dz))[tid];
    acc.x *= inv * nv.x;
    acc.y *= inv * nv.y;
    ((float2*)ctxs)[tid] = acc;
    __syncthreads();
    // av[b, h*64+j] = ctxs . wv[h*64+j, :]
    const float* wvl = wv + ((size_t)l * Dz + (size_t)h * 64) * Dz;
    const float2* c2 = (const float2*)ctxs;
#pragma unroll
    for (int it = 0; it < 8; it++) {
        int j = w * 8 + it;
        const float2* wr2 = (const float2*)(wvl + (size_t)j * Dz);
        float2 a = make_float2(0.f, 0.f);
#pragma unroll
        for (int kq = 0; kq < 8; kq++) { int idx = lane + 32 * kq; fma2(a, c2[idx], wr2[idx]); }
        float rsum = wred(a.x + a.y);
        if (lane == 0) g_av[(size_t)b * Dz + h * 64 + j] = rsum;
    }
}

// ---------------- ff2 partial reduce + bias + residual -> new x ----------------
__global__ __launch_bounds__(256) void k_ff2red(const float* __restrict__ b2l) {
    int b = blockIdx.x, tid = threadIdx.x;
    float2 s = ((const float2*)(g_part + (size_t)b * Dz))[tid];
#pragma unroll
    for (int ks = 1; ks < 4; ks++) {
        float2 p = ((const float2*)(g_part + (size_t)ks * Bz * Dz + (size_t)b * Dz))[tid];
        s.x += p.x; s.y += p.y;
    }
    float2 bb = ((const float2*)b2l)[tid];
    float2 hh = ((const float2*)(g_h + (size_t)b * Dz))[tid];
    ((float2*)(g_x + (size_t)b * Dz))[tid] = make_float2(s.x + bb.x + hh.x, s.y + bb.y + hh.y);
}

// ---------------- final ----------------
__global__ __launch_bounds__(256) void k_final(const float* __restrict__ summary,
                                               const float* __restrict__ onw,
                                               float* __restrict__ out_deter,
                                               float* __restrict__ out_summ) {
    int t = blockIdx.x, b = blockIdx.y, tid = threadIdx.x, w = tid >> 5, lane = tid & 31;
    __shared__ float row[Dz];
    __shared__ float red[9];
    const float* src = (t < Tz - 1) ? (summary + ((size_t)b * Tz + t + 1) * Dz) : (g_x + b * Dz);
    float ss = 0.f;
    for (int i = tid; i < Dz; i += 256) { float vv = src[i]; row[i] = vv; ss = fmaf(vv, vv, ss); }
    ss = wred(ss);
    if (lane == 0) red[w] = ss;
    __syncthreads();
    if (tid == 0) { float tt = 0; for (int i = 0; i < 8; i++) tt += red[i]; red[8] = rsqrtf(tt / 512.f + EPSRN); }
    __syncthreads();
    float rstd = red[8];
    for (int i = tid; i < Dz; i += 256) {
        out_summ[((size_t)b * Tz + t) * Dz + i] = row[i];
        out_deter[(size_t)b * (Tz * Dz) + t * Dz + i] = row[i] * rstd * onw[i];
    }
}

// ---------------- launch ----------------
extern "C" void kernel_launch(void* const* d_in, const int* in_sizes, int n_in,
                              void* d_out, int out_size) {
    (void)in_sizes; (void)n_in; (void)out_size;
    const float* stoch      = (const float*)d_in[0];
    const float* action     = (const float*)d_in[1];
    const float* cache      = (const float*)d_in[2];
    const float* summary    = (const float*)d_in[3];
    const float* in_w       = (const float*)d_in[4];
    const float* in_b       = (const float*)d_in[5];
    const float* in_norm_w  = (const float*)d_in[6];
    const float* n1w        = (const float*)d_in[7];
    const float* wq         = (const float*)d_in[8];
    const float* wk         = (const float*)d_in[9];
    const float* wv         = (const float*)d_in[10];
    const float* wr         = (const float*)d_in[11];
    const float* wo         = (const float*)d_in[12];
    const float* u          = (const float*)d_in[13];
    const float* v          = (const float*)d_in[14];
    const float* n2w        = (const float*)d_in[15];
    const float* ff_w1      = (const float*)d_in[16];
    const float* ff_b1      = (const float*)d_in[17];
    const float* ff_w2      = (const float*)d_in[18];
    const float* ff_b2      = (const float*)d_in[19];
    const float* out_norm_w = (const float*)d_in[20];

    float* out = (float*)d_out;
    float* out_deter = out;
    float* out_cache = out + (size_t)Bz * Tz * Dz;
    float* out_summ  = out_cache + (size_t)NL * Bz * Cz * Dz;

    float *p_cat, *p_tok, *p_x, *p_quk, *p_qur, *p_qkw, *p_rv, *p_bd,
          *p_rel, *p_av, *p_h, *p_ff, *p_part;
    cudaGetSymbolAddress((void**)&p_cat,  g_cat);
    cudaGetSymbolAddress((void**)&p_tok,  g_tok);
    cudaGetSymbolAddress((void**)&p_x,    g_x);
    cudaGetSymbolAddress((void**)&p_quk,  g_quk);
    cudaGetSymbolAddress((void**)&p_qur,  g_qur);
    cudaGetSymbolAddress((void**)&p_qkw,  g_qkw);
    cudaGetSymbolAddress((void**)&p_rv,   g_rv);
    cudaGetSymbolAddress((void**)&p_bd,   g_bd);
    cudaGetSymbolAddress((void**)&p_rel,  g_rel);
    cudaGetSymbolAddress((void**)&p_av,   g_av);
    cudaGetSymbolAddress((void**)&p_h,    g_h);
    cudaGetSymbolAddress((void**)&p_ff,   g_ff);
    cudaGetSymbolAddress((void**)&p_part, g_part);

    k_rel<<<LKV, 512>>>();
    k_prep<<<Bz, 256>>>(stoch, action);
    // tok = cat @ in_w^T + in_b
    k_mm<<<8, 256>>>(p_cat, SAz, 0, 0, in_w, SAz, 0, 0, p_tok, Dz, 0,
                     SAz, Dz, 5, in_b, nullptr, nullptr, nullptr,
                     nullptr, nullptr, nullptr, 0);
    k_silu<<<Bz, 256>>>(in_norm_w);

    for (int l = 0; l < NL; l++) {
        float* nc_l = out_cache + (size_t)l * Bz * Cz * Dz;
        const float* wql = wq + (size_t)l * Dz * Dz;
        const float* wkl = wk + (size_t)l * Dz * Dz;
        const float* wvl = wv;
        const float* wrl = wr + (size_t)l * Dz * Dz;
        const float* wol = wo + (size_t)l * Dz * Dz;

        // Q = rmsnorm(x)*n1 @ wq^T (fused rmsnorm); Quk = Q+u, Qur = Q+v
        k_mm<<<8, 256>>>(p_x, Dz, 0, 0, wql, Dz, 0, 0, p_quk, Dz, 0,
                         Dz, Dz, 3, u + l * Dz, v + l * Dz, p_qur, n1w + l * Dz,
                         nullptr, nullptr, nullptr, 0);
        // fused pair: z=0 qkw = Quk@wk_head * n1 ; z=1 rv = Qur@wr_head
        k_mm<<<dim3(8, 8, 2), 256>>>(p_quk, Dz, 0, 64, wkl, Dz, 64 * Dz, 1,
                                     p_qkw, Hz * Dz, Dz, 64, Dz, 4,
                                     n1w + l * Dz, nullptr, nullptr, nullptr,
                                     p_qur, wrl, p_rv, 0);
        // bd(512x1025) = rv @ rel^T
        k_mm<<<dim3(17, 8), 256>>>(p_rv, Dz, 0, 64 * Dz, p_rel, Dz, 0, 0,
                                   p_bd, BDS, 64 * BDS, Dz, LKV, 0,
                                   nullptr, nullptr, nullptr, nullptr,
                                   nullptr, nullptr, nullptr, 0);
        k_att<<<dim3(NCH, Bz), 256>>>(l, cache, nc_l);
        k_mav<<<dim3(Bz, Hz), 256>>>(l, n1w, wvl + (size_t)l * Dz * Dz - (size_t)l * Dz * Dz);
        // h = x + av @ wo^T
        k_mm<<<8, 256>>>(p_av, Dz, 0, 0, wol, Dz, 0, 0, p_h, Dz, 0,
                         Dz, Dz, 6, nullptr, p_x, nullptr, nullptr,
                         nullptr, nullptr, nullptr, 0);
        // ff hidden = gelu(rmsnorm(h)*n2 @ w1^T + b1) (fused rmsnorm)
        k_mm<<<32, 256>>>(p_h, Dz, 0, 0, ff_w1 + (size_t)l * FFz * Dz, Dz, 0, 0,
                          p_ff, FFz, 0, Dz, FFz, 1,
                          ff_b1 + (size_t)l * FFz, nullptr, nullptr, n2w + l * Dz,
                          nullptr, nullptr, nullptr, 0);
        // ff2 split-K partials
        k_mm<<<dim3(8, 4), 256>>>(p_ff, FFz, 0, 512, ff_w2 + (size_t)l * Dz * FFz, FFz, 512, 0,
                                  p_part, Dz, Bz * Dz, 512, Dz, 0,
                                  nullptr, nullptr, nullptr, nullptr,
                                  nullptr, nullptr, nullptr, 0);
        k_ff2red<<<Bz, 256>>>(ff_b2 + (size_t)l * Dz);
    }
    k_final<<<dim3(Tz, Bz), 256>>>(summary, out_norm_w, out_deter, out_summ);
}